// round 15
// baseline (speedup 1.0000x reference)
#include <cuda_runtime.h>
#include <cuda_fp8.h>
#include <cstdint>

#define NROW 2048
#define NCOL 4096
#define NBATCH 4
#define CMAX 64
#define CCAP 256
#define CUT 24.0f

// ---------------- device scratch ----------
__device__ float    g_q   [(size_t)NBATCH * NROW * NCOL];            // 128 MB fp32
__device__ __align__(16) uint8_t g_q8[(size_t)NBATCH * NROW * NCOL]; // 32 MB e4m3
__device__ uint32_t g_rowmin_u[NBATCH * NROW];
__device__ int      g_ccnt [NBATCH * NROW];
__device__ int      g_cidx2[(size_t)NBATCH * NROW * CCAP];           // 8 MB
__device__ float    g_ce   [(size_t)NBATCH * NROW * CCAP];           // 8 MB

__device__ __forceinline__ uint32_t fkey(float f) {
    uint32_t u = __float_as_uint(f);
    return (u & 0x80000000u) ? ~u : (u | 0x80000000u);
}
__device__ __forceinline__ float fdecode(uint32_t k) {
    return (k & 0x80000000u) ? __uint_as_float(k ^ 0x80000000u) : __uint_as_float(~k);
}

// ---------------- kernel 1: space_to_channel pack + fp8 quantize -----------
__global__ void __launch_bounds__(256) pack_kernel(const float* __restrict__ x) {
    unsigned tid = blockIdx.x * 256u + threadIdx.x;
    if (tid < NBATCH * NROW) { g_rowmin_u[tid] = 0xFFFFFFFFu; g_ccnt[tid] = 0; }
    int d4 = tid & 15;
    int h  = (tid >> 4) & 63;
    int w  = (tid >> 10) & 63;
    int c  = (tid >> 16) & 31;
    int b  = tid >> 21;
    float4 v = reinterpret_cast<const float4*>(x)[tid];
    int n   = ((w >> 2) << 8) + (((w & 3) << 2) + (h >> 4)) * 16 + d4;
    int chb = ((h & 15) << 7) + c;
    size_t base = ((size_t)(b * NROW + chb)) * NCOL + n;
    float vv[4] = {v.x, v.y, v.z, v.w};
#pragma unroll
    for (int j = 0; j < 4; j++) {
        size_t idx = base + (size_t)j * 32 * NCOL;
        float f = vv[j];
        g_q[idx] = f;
        g_q8[idx] = (uint8_t)__nv_cvt_float_to_fp8(f, __NV_SATFINITE, __NV_E4M3);
    }
}

// ---------------- kernel 2: approx Gram (e4m3) + register candidate push ---
// Mainloop byte-identical to R11/R13. Epilogue: shuffle minima (proven) then
// direct push of v < tile_min + CUT from accumulators to per-row lists.
#define MMA_FP8(cacc, aa, bb) \
    asm volatile( \
        "mma.sync.aligned.m16n8k32.row.col.f32.e4m3.e4m3.f32 " \
        "{%0,%1,%2,%3},{%4,%5,%6,%7},{%8,%9},{%0,%1,%2,%3};\n" \
        : "+f"(cacc[0]), "+f"(cacc[1]), "+f"(cacc[2]), "+f"(cacc[3]) \
        : "r"(aa[0]), "r"(aa[1]), "r"(aa[2]), "r"(aa[3]), "r"(bb[0]), "r"(bb[1]))

__global__ void __launch_bounds__(256, 2) gram_kernel() {
    int b = blockIdx.y;
    int t = blockIdx.x;
    int ti = 0;
    while (t >= 16 - ti) { t -= 16 - ti; ti++; }
    int tj = ti + t;                                  // ti <= tj

    extern __shared__ unsigned char smem_raw[];
    uint8_t* sm = (uint8_t*)smem_raw;
    const int ARR = 128 * 80;
    const int STG = 2 * ARR;

    int tid  = threadIdx.x;
    int lane = tid & 31;
    int warp = tid >> 5;
    int wm = warp >> 2;
    int wn = warp & 3;

    size_t rowA = (size_t)(b * NROW + ti * 128);
    size_t rowB = (size_t)(b * NROW + tj * 128);

    auto load_stage = [&](int stage, int chunk) {
#pragma unroll
        for (int it = 0; it < 4; it++) {
            int u   = it * 256 + tid;
            int arr = u >> 9;
            int rr  = (u >> 2) & 127;
            int seg = (u & 3);
            size_t row = (arr ? rowB : rowA) + rr;
            const uint8_t* gp = g_q8 + row * NCOL + chunk * 64 + seg * 16;
            unsigned sp = (unsigned)__cvta_generic_to_shared(
                sm + stage * STG + arr * ARR + rr * 80 + seg * 16);
            asm volatile("cp.async.cg.shared.global [%0], [%1], 16;\n"
                         :: "r"(sp), "l"(gp));
        }
    };

    float acc[4][4][4];
#pragma unroll
    for (int a = 0; a < 4; a++)
#pragma unroll
        for (int bq = 0; bq < 4; bq++)
#pragma unroll
            for (int r = 0; r < 4; r++) acc[a][bq][r] = 0.f;

    const int KT = NCOL / 64;
    load_stage(0, 0);
    asm volatile("cp.async.commit_group;\n");
    load_stage(1, 1);
    asm volatile("cp.async.commit_group;\n");

    for (int kt = 0; kt < KT; kt++) {
        if (kt + 2 < KT) {
            load_stage((kt + 2) % 3, kt + 2);
            asm volatile("cp.async.commit_group;\n");
            asm volatile("cp.async.wait_group 2;\n");
        } else if (kt + 1 < KT) {
            asm volatile("cp.async.wait_group 1;\n");
        } else {
            asm volatile("cp.async.wait_group 0;\n");
        }
        __syncthreads();
        const uint8_t* st = sm + (kt % 3) * STG;

#pragma unroll
        for (int ks = 0; ks < 2; ks++) {
            unsigned ahi[4][4], bhi[4][2];
#pragma unroll
            for (int mt = 0; mt < 4; mt++) {
                int r    = wm * 64 + mt * 16 + (lane & 15);
                int coff = ks * 32 + ((lane >> 4) << 4);
                unsigned ah = (unsigned)__cvta_generic_to_shared(st + r * 80 + coff);
                asm volatile("ldmatrix.sync.aligned.m8n8.x4.shared.b16 {%0,%1,%2,%3}, [%4];\n"
                    : "=r"(ahi[mt][0]), "=r"(ahi[mt][1]), "=r"(ahi[mt][2]), "=r"(ahi[mt][3])
                    : "r"(ah));
            }
#pragma unroll
            for (int nt = 0; nt < 4; nt++) {
                int lb   = lane & 15;
                int r    = wn * 32 + nt * 8 + (lb & 7);
                int coff = ks * 32 + (((lb >> 3) & 1) << 4);
                unsigned bh = (unsigned)__cvta_generic_to_shared(st + ARR + r * 80 + coff);
                asm volatile("ldmatrix.sync.aligned.m8n8.x2.shared.b16 {%0,%1}, [%2];\n"
                    : "=r"(bhi[nt][0]), "=r"(bhi[nt][1]) : "r"(bh));
            }
#pragma unroll
            for (int mt = 0; mt < 4; mt++)
#pragma unroll
                for (int nt = 0; nt < 4; nt++)
                    MMA_FP8(acc[mt][nt], ahi[mt], bhi[nt]);
        }
        __syncthreads();
    }

    // ---- epilogue v3: shuffle minima + direct register push (no e16) ----
    uint32_t* s_rmin = (uint32_t*)smem_raw;   // 128
    uint32_t* s_cmin = s_rmin + 128;          // 128

    if (tid < 128) s_rmin[tid] = 0xFFFFFFFFu;
    else           s_cmin[tid - 128] = 0xFFFFFFFFu;
    __syncthreads();

    int lr = lane >> 2, lc = (lane & 3) * 2;

    // row minima (reduce over nt + lc lanes)
#pragma unroll
    for (int mt = 0; mt < 4; mt++) {
        float m0 = 3.4e38f, m1 = 3.4e38f;
#pragma unroll
        for (int nt = 0; nt < 4; nt++) {
            m0 = fminf(m0, fminf(acc[mt][nt][0], acc[mt][nt][1]));
            m1 = fminf(m1, fminf(acc[mt][nt][2], acc[mt][nt][3]));
        }
        m0 = fminf(m0, __shfl_xor_sync(0xFFFFFFFFu, m0, 1));
        m0 = fminf(m0, __shfl_xor_sync(0xFFFFFFFFu, m0, 2));
        m1 = fminf(m1, __shfl_xor_sync(0xFFFFFFFFu, m1, 1));
        m1 = fminf(m1, __shfl_xor_sync(0xFFFFFFFFu, m1, 2));
        if ((lane & 3) == 0) {
            int r0 = wm * 64 + mt * 16 + lr;
            atomicMin(&s_rmin[r0],     fkey(m0));
            atomicMin(&s_rmin[r0 + 8], fkey(m1));
        }
    }
    // col minima (reduce over mt + lr lanes)
#pragma unroll
    for (int nt = 0; nt < 4; nt++) {
        float c0 = 3.4e38f, c1 = 3.4e38f;
#pragma unroll
        for (int mt = 0; mt < 4; mt++) {
            c0 = fminf(c0, fminf(acc[mt][nt][0], acc[mt][nt][2]));
            c1 = fminf(c1, fminf(acc[mt][nt][1], acc[mt][nt][3]));
        }
#pragma unroll
        for (int o = 4; o <= 16; o <<= 1) {
            c0 = fminf(c0, __shfl_xor_sync(0xFFFFFFFFu, c0, o));
            c1 = fminf(c1, __shfl_xor_sync(0xFFFFFFFFu, c1, o));
        }
        if (lane < 4) {
            int cc = wn * 32 + nt * 8 + lane * 2;
            atomicMin(&s_cmin[cc],     fkey(c0));
            atomicMin(&s_cmin[cc + 1], fkey(c1));
        }
    }
    __syncthreads();

    if (tid < 128) atomicMin(&g_rowmin_u[b * NROW + ti * 128 + tid], s_rmin[tid]);
    else if (ti != tj)
        atomicMin(&g_rowmin_u[b * NROW + tj * 128 + (tid - 128)], s_cmin[tid - 128]);

    // candidate push straight from accumulator registers
#pragma unroll
    for (int mt = 0; mt < 4; mt++)
#pragma unroll
        for (int nt = 0; nt < 4; nt++)
#pragma unroll
            for (int q = 0; q < 4; q++) {
                int r = wm * 64 + mt * 16 + lr + ((q >> 1) << 3);
                int c = wn * 32 + nt * 8 + lc + (q & 1);
                float v = acc[mt][nt][q];
                if (v < fdecode(s_rmin[r]) + CUT) {
                    int grow = b * NROW + ti * 128 + r;
                    int pos = atomicAdd(&g_ccnt[grow], 1);
                    if (pos < CCAP) {
                        g_cidx2[(size_t)grow * CCAP + pos] = tj * 128 + c;
                        g_ce   [(size_t)grow * CCAP + pos] = v;
                    }
                }
                if (ti != tj && v < fdecode(s_cmin[c]) + CUT) {
                    int grow = b * NROW + tj * 128 + c;
                    int pos = atomicAdd(&g_ccnt[grow], 1);
                    if (pos < CCAP) {
                        g_cidx2[(size_t)grow * CCAP + pos] = ti * 128 + r;
                        g_ce   [(size_t)grow * CCAP + pos] = v;
                    }
                }
            }
}

// ---- kernel 3: FUSED filter + exact refine + softmax + sparse AV + c2s ----
// Phases A/B/C byte-identical to R13 (best); collect now reads per-row lists.
__global__ void __launch_bounds__(512) fuse_kernel(const float* __restrict__ gamma_ptr,
                                                   float* __restrict__ out) {
    int blk = blockIdx.x;               // 2048 blocks
    int cs = blk & 31;
    int e2 = (blk >> 5) & 15;
    int b  = blk >> 9;
    int t = threadIdx.x;
    int lane = t & 31;
    float gamma = __ldg(gamma_ptr);

    __shared__ int   cidx[4 * CMAX];
    __shared__ float exd [4 * CMAX];
    __shared__ int   cnts[4];

    int rl[4];
#pragma unroll
    for (int e1 = 0; e1 < 4; e1++) rl[e1] = e2 * 128 + e1 * 32 + cs;

    if (t < 4) cnts[t] = 0;
    if (t < 4 * CMAX) exd[t] = 0.f;
    __syncthreads();

    // filter pre-collected candidates with exact global threshold
#pragma unroll
    for (int e1 = 0; e1 < 4; e1++) {
        int grow = b * NROW + rl[e1];
        float thr = fdecode(g_rowmin_u[grow]) + CUT;
        int nc = g_ccnt[grow]; if (nc > CCAP) nc = CCAP;
        for (int k = t; k < nc; k += 512) {
            float v = g_ce[(size_t)grow * CCAP + k];
            if (v < thr) {
                int pos = atomicAdd(&cnts[e1], 1);
                if (pos < CMAX) cidx[e1 * CMAX + pos] = g_cidx2[(size_t)grow * CCAP + k];
            }
        }
    }
    __syncthreads();

    const float4* qb4 = reinterpret_cast<const float4*>(g_q + (size_t)b * NROW * NCOL);

    // Phase A: exact fp32 dots, block-wide (each thread covers cols t, t+512)
#pragma unroll
    for (int e1 = 0; e1 < 4; e1++) {
        int cnt = cnts[e1]; if (cnt > CMAX) cnt = CMAX;
        const float4* qi = qb4 + (size_t)rl[e1] * 1024;
        float4 a0 = __ldg(qi + t);
        float4 a1 = __ldg(qi + t + 512);
        for (int k = 0; k < cnt; k++) {
            const float4* qj = qb4 + (size_t)cidx[e1 * CMAX + k] * 1024;
            float4 v0 = __ldg(qj + t);
            float4 v1 = __ldg(qj + t + 512);
            float s = a0.x * v0.x + a0.y * v0.y + a0.z * v0.z + a0.w * v0.w
                    + a1.x * v1.x + a1.y * v1.y + a1.z * v1.z + a1.w * v1.w;
#pragma unroll
            for (int o = 16; o > 0; o >>= 1) s += __shfl_xor_sync(0xFFFFFFFFu, s, o);
            if (lane == 0) atomicAdd(&exd[e1 * CMAX + k], s);
        }
    }
    __syncthreads();

    // Phase B: softmax + prune (one thread per e1, in-place compaction)
    if (t < 4) {
        int e1 = t;
        int cnt = cnts[e1]; if (cnt > CMAX) cnt = CMAX;
        float m = 3.4e38f;
        for (int c = 0; c < cnt; c++) m = fminf(m, exd[e1 * CMAX + c]);
        float Z = 0.f;
        for (int c = 0; c < cnt; c++) {
            float w = __expf(m - exd[e1 * CMAX + c]);
            exd[e1 * CMAX + c] = w; Z += w;
        }
        float inv = 1.0f / Z;
        int newc = 0;
        for (int c = 0; c < cnt; c++) {
            float w = exd[e1 * CMAX + c] * inv;
            if (w > 3e-7f) {
                cidx[e1 * CMAX + newc] = cidx[e1 * CMAX + c];
                exd [e1 * CMAX + newc] = w;
                newc++;
            }
        }
        cnts[e1] = newc;
    }
    __syncthreads();

    // Phase C: per-half weighted combine (rows L2-hot) + c2s store
    size_t obase = ((size_t)(b * 32 + cs)) * 64 * 64 * 64;
    int wq = e2 >> 2;
    int hq = (e2 & 3) * 16;

#pragma unroll
    for (int h = 0; h < 2; h++) {
        int f = h * 512 + t;               // float4 column 0..1023
        float res[4][4];
#pragma unroll
        for (int e1 = 0; e1 < 4; e1++) {
            int cnt = cnts[e1];
            float4 acc = make_float4(0.f, 0.f, 0.f, 0.f);
            for (int k = 0; k < cnt; k++) {
                float4 v = __ldg(&qb4[(size_t)cidx[e1 * CMAX + k] * 1024 + f]);
                float w = exd[e1 * CMAX + k];
                acc.x += w * v.x; acc.y += w * v.y;
                acc.z += w * v.z; acc.w += w * v.w;
            }
            float4 y = __ldg(&qb4[(size_t)rl[e1] * 1024 + f]);
            res[e1][0] = gamma * acc.x + y.x;
            res[e1][1] = gamma * acc.y + y.y;
            res[e1][2] = gamma * acc.z + y.z;
            res[e1][3] = gamma * acc.w + y.w;
        }
        int n0 = f * 4;
        int wd = n0 >> 8, hd = (n0 >> 4) & 15, dd0 = n0 & 15;
        int Wn = wd * 4 + wq;
        int Hn = hq + hd;
        size_t oi = obase + (size_t)Wn * 4096 + (size_t)Hn * 64 + dd0 * 4;
#pragma unroll
        for (int nn = 0; nn < 4; nn++) {
            *reinterpret_cast<float4*>(out + oi + nn * 4) =
                make_float4(res[0][nn], res[1][nn], res[2][nn], res[3][nn]);
        }
    }
}

// ---------------- launch ---------------------------------------------------
extern "C" void kernel_launch(void* const* d_in, const int* in_sizes, int n_in,
                              void* d_out, int out_size) {
    const float* x     = (const float*)d_in[0];
    const float* gamma = (const float*)d_in[1];
    float* out = (float*)d_out;

    pack_kernel<<<32768, 256>>>(x);

    cudaFuncSetAttribute(gram_kernel, cudaFuncAttributeMaxDynamicSharedMemorySize, 61440);
    gram_kernel<<<dim3(136, 4), 256, 61440>>>();

    fuse_kernel<<<2048, 512>>>(gamma, out);
}

// round 16
// speedup vs baseline: 1.1760x; 1.1760x over previous
#include <cuda_runtime.h>
#include <cuda_fp8.h>
#include <cuda_fp16.h>
#include <cstdint>

#define NROW 2048
#define NCOL 4096
#define NBATCH 4
#define CMAX 64
#define CUT 21.0f

// ---------------- device scratch ----------
__device__ float    g_q   [(size_t)NBATCH * NROW * NCOL];            // 128 MB fp32
__device__ __align__(16) uint8_t g_q8[(size_t)NBATCH * NROW * NCOL]; // 32 MB e4m3
__device__ __align__(16) __half  g_e16[(size_t)NBATCH * NROW * NROW];// 32 MB fp16
__device__ uint32_t g_rowmin_u[NBATCH * NROW];

__device__ __forceinline__ uint32_t fkey(float f) {
    uint32_t u = __float_as_uint(f);
    return (u & 0x80000000u) ? ~u : (u | 0x80000000u);
}
__device__ __forceinline__ float fdecode(uint32_t k) {
    return (k & 0x80000000u) ? __uint_as_float(k ^ 0x80000000u) : __uint_as_float(~k);
}

// ---------------- kernel 1: space_to_channel pack + fp8 quantize -----------
__global__ void __launch_bounds__(256) pack_kernel(const float* __restrict__ x) {
    unsigned tid = blockIdx.x * 256u + threadIdx.x;
    if (tid < NBATCH * NROW) g_rowmin_u[tid] = 0xFFFFFFFFu;
    int d4 = tid & 15;
    int h  = (tid >> 4) & 63;
    int w  = (tid >> 10) & 63;
    int c  = (tid >> 16) & 31;
    int b  = tid >> 21;
    float4 v = reinterpret_cast<const float4*>(x)[tid];
    int n   = ((w >> 2) << 8) + (((w & 3) << 2) + (h >> 4)) * 16 + d4;
    int chb = ((h & 15) << 7) + c;
    size_t base = ((size_t)(b * NROW + chb)) * NCOL + n;
    float vv[4] = {v.x, v.y, v.z, v.w};
#pragma unroll
    for (int j = 0; j < 4; j++) {
        size_t idx = base + (size_t)j * 32 * NCOL;
        float f = vv[j];
        g_q[idx] = f;
        g_q8[idx] = (uint8_t)__nv_cvt_float_to_fp8(f, __NV_SATFINITE, __NV_E4M3);
    }
}

// ---------------- kernel 2: approx Gram (e4m3, fp32 accum) -----------------
// (byte-identical to R13: occ-2, fp16 epilogue tile, shuffle minima)
#define MMA_FP8(cacc, aa, bb) \
    asm volatile( \
        "mma.sync.aligned.m16n8k32.row.col.f32.e4m3.e4m3.f32 " \
        "{%0,%1,%2,%3},{%4,%5,%6,%7},{%8,%9},{%0,%1,%2,%3};\n" \
        : "+f"(cacc[0]), "+f"(cacc[1]), "+f"(cacc[2]), "+f"(cacc[3]) \
        : "r"(aa[0]), "r"(aa[1]), "r"(aa[2]), "r"(aa[3]), "r"(bb[0]), "r"(bb[1]))

__global__ void __launch_bounds__(256, 2) gram_kernel() {
    int b = blockIdx.y;
    int t = blockIdx.x;
    int ti = 0;
    while (t >= 16 - ti) { t -= 16 - ti; ti++; }
    int tj = ti + t;                                  // ti <= tj

    extern __shared__ unsigned char smem_raw[];
    uint8_t* sm = (uint8_t*)smem_raw;
    const int ARR = 128 * 80;
    const int STG = 2 * ARR;

    int tid  = threadIdx.x;
    int lane = tid & 31;
    int warp = tid >> 5;
    int wm = warp >> 2;
    int wn = warp & 3;

    size_t rowA = (size_t)(b * NROW + ti * 128);
    size_t rowB = (size_t)(b * NROW + tj * 128);

    auto load_stage = [&](int stage, int chunk) {
#pragma unroll
        for (int it = 0; it < 4; it++) {
            int u   = it * 256 + tid;
            int arr = u >> 9;
            int rr  = (u >> 2) & 127;
            int seg = (u & 3);
            size_t row = (arr ? rowB : rowA) + rr;
            const uint8_t* gp = g_q8 + row * NCOL + chunk * 64 + seg * 16;
            unsigned sp = (unsigned)__cvta_generic_to_shared(
                sm + stage * STG + arr * ARR + rr * 80 + seg * 16);
            asm volatile("cp.async.cg.shared.global [%0], [%1], 16;\n"
                         :: "r"(sp), "l"(gp));
        }
    };

    float acc[4][4][4];
#pragma unroll
    for (int a = 0; a < 4; a++)
#pragma unroll
        for (int bq = 0; bq < 4; bq++)
#pragma unroll
            for (int r = 0; r < 4; r++) acc[a][bq][r] = 0.f;

    const int KT = NCOL / 64;
    load_stage(0, 0);
    asm volatile("cp.async.commit_group;\n");
    load_stage(1, 1);
    asm volatile("cp.async.commit_group;\n");

    for (int kt = 0; kt < KT; kt++) {
        if (kt + 2 < KT) {
            load_stage((kt + 2) % 3, kt + 2);
            asm volatile("cp.async.commit_group;\n");
            asm volatile("cp.async.wait_group 2;\n");
        } else if (kt + 1 < KT) {
            asm volatile("cp.async.wait_group 1;\n");
        } else {
            asm volatile("cp.async.wait_group 0;\n");
        }
        __syncthreads();
        const uint8_t* st = sm + (kt % 3) * STG;

#pragma unroll
        for (int ks = 0; ks < 2; ks++) {
            unsigned ahi[4][4], bhi[4][2];
#pragma unroll
            for (int mt = 0; mt < 4; mt++) {
                int r    = wm * 64 + mt * 16 + (lane & 15);
                int coff = ks * 32 + ((lane >> 4) << 4);
                unsigned ah = (unsigned)__cvta_generic_to_shared(st + r * 80 + coff);
                asm volatile("ldmatrix.sync.aligned.m8n8.x4.shared.b16 {%0,%1,%2,%3}, [%4];\n"
                    : "=r"(ahi[mt][0]), "=r"(ahi[mt][1]), "=r"(ahi[mt][2]), "=r"(ahi[mt][3])
                    : "r"(ah));
            }
#pragma unroll
            for (int nt = 0; nt < 4; nt++) {
                int lb   = lane & 15;
                int r    = wn * 32 + nt * 8 + (lb & 7);
                int coff = ks * 32 + (((lb >> 3) & 1) << 4);
                unsigned bh = (unsigned)__cvta_generic_to_shared(st + ARR + r * 80 + coff);
                asm volatile("ldmatrix.sync.aligned.m8n8.x2.shared.b16 {%0,%1}, [%2];\n"
                    : "=r"(bhi[nt][0]), "=r"(bhi[nt][1]) : "r"(bh));
            }
#pragma unroll
            for (int mt = 0; mt < 4; mt++)
#pragma unroll
                for (int nt = 0; nt < 4; nt++)
                    MMA_FP8(acc[mt][nt], ahi[mt], bhi[nt]);
        }
        __syncthreads();
    }

    // ---- epilogue: fp16 tile in smem + register-shuffle minima ----
    uint32_t* hs     = (uint32_t*)smem_raw;   // 128 x 66 uint32 (fp16x2 tile)
    __half*   hh     = (__half*)hs;           // same, half view (stride 132)
    uint32_t* s_rmin = hs + 128 * 66;         // 128
    uint32_t* s_cmin = s_rmin + 128;          // 128

    if (tid < 128) s_rmin[tid] = 0xFFFFFFFFu;
    else           s_cmin[tid - 128] = 0xFFFFFFFFu;
    __syncthreads();

    int lr = lane >> 2, lc = (lane & 3) * 2;

#pragma unroll
    for (int mt = 0; mt < 4; mt++)
#pragma unroll
        for (int nt = 0; nt < 4; nt++) {
            int r = wm * 64 + mt * 16 + lr;
            int c = wn * 32 + nt * 8 + lc;
            __half2 h0 = __floats2half2_rn(acc[mt][nt][0], acc[mt][nt][1]);
            __half2 h1 = __floats2half2_rn(acc[mt][nt][2], acc[mt][nt][3]);
            *reinterpret_cast<__half2*>(&hs[r * 66 + (c >> 1)])       = h0;
            *reinterpret_cast<__half2*>(&hs[(r + 8) * 66 + (c >> 1)]) = h1;
        }

#pragma unroll
    for (int mt = 0; mt < 4; mt++) {
        float m0 = 3.4e38f, m1 = 3.4e38f;
#pragma unroll
        for (int nt = 0; nt < 4; nt++) {
            m0 = fminf(m0, fminf(acc[mt][nt][0], acc[mt][nt][1]));
            m1 = fminf(m1, fminf(acc[mt][nt][2], acc[mt][nt][3]));
        }
        m0 = fminf(m0, __shfl_xor_sync(0xFFFFFFFFu, m0, 1));
        m0 = fminf(m0, __shfl_xor_sync(0xFFFFFFFFu, m0, 2));
        m1 = fminf(m1, __shfl_xor_sync(0xFFFFFFFFu, m1, 1));
        m1 = fminf(m1, __shfl_xor_sync(0xFFFFFFFFu, m1, 2));
        if ((lane & 3) == 0) {
            int r0 = wm * 64 + mt * 16 + lr;
            atomicMin(&s_rmin[r0],     fkey(m0));
            atomicMin(&s_rmin[r0 + 8], fkey(m1));
        }
    }
#pragma unroll
    for (int nt = 0; nt < 4; nt++) {
        float c0 = 3.4e38f, c1 = 3.4e38f;
#pragma unroll
        for (int mt = 0; mt < 4; mt++) {
            c0 = fminf(c0, fminf(acc[mt][nt][0], acc[mt][nt][2]));
            c1 = fminf(c1, fminf(acc[mt][nt][1], acc[mt][nt][3]));
        }
#pragma unroll
        for (int o = 4; o <= 16; o <<= 1) {
            c0 = fminf(c0, __shfl_xor_sync(0xFFFFFFFFu, c0, o));
            c1 = fminf(c1, __shfl_xor_sync(0xFFFFFFFFu, c1, o));
        }
        if (lane < 4) {
            int cc = wn * 32 + nt * 8 + lane * 2;
            atomicMin(&s_cmin[cc],     fkey(c0));
            atomicMin(&s_cmin[cc + 1], fkey(c1));
        }
    }
    __syncthreads();

    if (tid < 128) atomicMin(&g_rowmin_u[b * NROW + ti * 128 + tid], s_rmin[tid]);
    else if (ti != tj)
        atomicMin(&g_rowmin_u[b * NROW + tj * 128 + (tid - 128)], s_cmin[tid - 128]);

    size_t ebase = (size_t)b * NROW * NROW;
    for (int u = tid; u < 8192; u += 256) {
        int r = u >> 6, c2 = u & 63;
        *reinterpret_cast<uint32_t*>(
            g_e16 + ebase + (size_t)(ti * 128 + r) * NROW + tj * 128 + 2 * c2) =
            hs[r * 66 + c2];
    }
    if (ti != tj) {
        for (int u = tid; u < 8192; u += 256) {
            int r = u >> 6, c2 = u & 63;
            __half2 hv = __halves2half2(hh[(2 * c2) * 132 + r], hh[(2 * c2 + 1) * 132 + r]);
            *reinterpret_cast<__half2*>(
                g_e16 + ebase + (size_t)(tj * 128 + r) * NROW + ti * 128 + 2 * c2) = hv;
        }
    }
}

// ---- kernel 3: FUSED scan + exact refine + softmax + sparse AV + c2s ------
// (byte-identical to R13 fuse)
__global__ void __launch_bounds__(512) fuse_kernel(const float* __restrict__ gamma_ptr,
                                                   float* __restrict__ out) {
    int blk = blockIdx.x;               // 2048 blocks
    int cs = blk & 31;
    int e2 = (blk >> 5) & 15;
    int b  = blk >> 9;
    int t = threadIdx.x;
    int lane = t & 31;
    float gamma = __ldg(gamma_ptr);

    __shared__ int   cidx[4 * CMAX];
    __shared__ float exd [4 * CMAX];
    __shared__ int   cnts[4];

    int rl[4];
#pragma unroll
    for (int e1 = 0; e1 < 4; e1++) rl[e1] = e2 * 128 + e1 * 32 + cs;

    if (t < 4) cnts[t] = 0;
    if (t < 4 * CMAX) exd[t] = 0.f;
    __syncthreads();

    // candidate collect from fp16 energy rows (exact global threshold)
#pragma unroll
    for (int e1 = 0; e1 < 4; e1++) {
        int grow = b * NROW + rl[e1];
        float thr = fdecode(g_rowmin_u[grow]) + CUT;
        uint2 ev = reinterpret_cast<const uint2*>(g_e16 + (size_t)grow * NROW)[t];
        uint32_t ww[2] = {ev.x, ev.y};
#pragma unroll
        for (int p = 0; p < 2; p++) {
            __half2 h2 = *reinterpret_cast<__half2*>(&ww[p]);
            float e0 = __low2float(h2), e1v = __high2float(h2);
            if (e0 < thr) {
                int pos = atomicAdd(&cnts[e1], 1);
                if (pos < CMAX) cidx[e1 * CMAX + pos] = t * 4 + 2 * p;
            }
            if (e1v < thr) {
                int pos = atomicAdd(&cnts[e1], 1);
                if (pos < CMAX) cidx[e1 * CMAX + pos] = t * 4 + 2 * p + 1;
            }
        }
    }
    __syncthreads();

    const float4* qb4 = reinterpret_cast<const float4*>(g_q + (size_t)b * NROW * NCOL);

    // Phase A: exact fp32 dots, block-wide (each thread covers cols t, t+512)
#pragma unroll
    for (int e1 = 0; e1 < 4; e1++) {
        int cnt = cnts[e1]; if (cnt > CMAX) cnt = CMAX;
        const float4* qi = qb4 + (size_t)rl[e1] * 1024;
        float4 a0 = __ldg(qi + t);
        float4 a1 = __ldg(qi + t + 512);
        for (int k = 0; k < cnt; k++) {
            const float4* qj = qb4 + (size_t)cidx[e1 * CMAX + k] * 1024;
            float4 v0 = __ldg(qj + t);
            float4 v1 = __ldg(qj + t + 512);
            float s = a0.x * v0.x + a0.y * v0.y + a0.z * v0.z + a0.w * v0.w
                    + a1.x * v1.x + a1.y * v1.y + a1.z * v1.z + a1.w * v1.w;
#pragma unroll
            for (int o = 16; o > 0; o >>= 1) s += __shfl_xor_sync(0xFFFFFFFFu, s, o);
            if (lane == 0) atomicAdd(&exd[e1 * CMAX + k], s);
        }
    }
    __syncthreads();

    // Phase B: softmax + prune (one thread per e1, in-place compaction)
    if (t < 4) {
        int e1 = t;
        int cnt = cnts[e1]; if (cnt > CMAX) cnt = CMAX;
        float m = 3.4e38f;
        for (int c = 0; c < cnt; c++) m = fminf(m, exd[e1 * CMAX + c]);
        float Z = 0.f;
        for (int c = 0; c < cnt; c++) {
            float w = __expf(m - exd[e1 * CMAX + c]);
            exd[e1 * CMAX + c] = w; Z += w;
        }
        float inv = 1.0f / Z;
        int newc = 0;
        for (int c = 0; c < cnt; c++) {
            float w = exd[e1 * CMAX + c] * inv;
            if (w > 3e-7f) {
                cidx[e1 * CMAX + newc] = cidx[e1 * CMAX + c];
                exd [e1 * CMAX + newc] = w;
                newc++;
            }
        }
        cnts[e1] = newc;
    }
    __syncthreads();

    // Phase C: per-half weighted combine (rows L2-hot) + c2s store
    size_t obase = ((size_t)(b * 32 + cs)) * 64 * 64 * 64;
    int wq = e2 >> 2;
    int hq = (e2 & 3) * 16;

#pragma unroll
    for (int h = 0; h < 2; h++) {
        int f = h * 512 + t;               // float4 column 0..1023
        float res[4][4];
#pragma unroll
        for (int e1 = 0; e1 < 4; e1++) {
            int cnt = cnts[e1];
            float4 acc = make_float4(0.f, 0.f, 0.f, 0.f);
            for (int k = 0; k < cnt; k++) {
                float4 v = __ldg(&qb4[(size_t)cidx[e1 * CMAX + k] * 1024 + f]);
                float w = exd[e1 * CMAX + k];
                acc.x += w * v.x; acc.y += w * v.y;
                acc.z += w * v.z; acc.w += w * v.w;
            }
            float4 y = __ldg(&qb4[(size_t)rl[e1] * 1024 + f]);
            res[e1][0] = gamma * acc.x + y.x;
            res[e1][1] = gamma * acc.y + y.y;
            res[e1][2] = gamma * acc.z + y.z;
            res[e1][3] = gamma * acc.w + y.w;
        }
        int n0 = f * 4;
        int wd = n0 >> 8, hd = (n0 >> 4) & 15, dd0 = n0 & 15;
        int Wn = wd * 4 + wq;
        int Hn = hq + hd;
        size_t oi = obase + (size_t)Wn * 4096 + (size_t)Hn * 64 + dd0 * 4;
#pragma unroll
        for (int nn = 0; nn < 4; nn++) {
            *reinterpret_cast<float4*>(out + oi + nn * 4) =
                make_float4(res[0][nn], res[1][nn], res[2][nn], res[3][nn]);
        }
    }
}

// ---------------- launch ---------------------------------------------------
extern "C" void kernel_launch(void* const* d_in, const int* in_sizes, int n_in,
                              void* d_out, int out_size) {
    const float* x     = (const float*)d_in[0];
    const float* gamma = (const float*)d_in[1];
    float* out = (float*)d_out;

    pack_kernel<<<32768, 256>>>(x);

    cudaFuncSetAttribute(gram_kernel, cudaFuncAttributeMaxDynamicSharedMemorySize, 61440);
    gram_kernel<<<dim3(136, 4), 256, 61440>>>();

    fuse_kernel<<<2048, 512>>>(gamma, out);
}

// round 17
// speedup vs baseline: 1.2056x; 1.0252x over previous
#include <cuda_runtime.h>
#include <cuda_fp8.h>
#include <cuda_fp16.h>
#include <cstdint>

#define NROW 2048
#define NCOL 4096
#define NBATCH 4
#define CMAX 64
#define CUT 21.0f

// ---------------- device scratch ----------
__device__ float    g_q   [(size_t)NBATCH * NROW * NCOL];            // 128 MB fp32
__device__ __align__(16) uint8_t g_q8[(size_t)NBATCH * NROW * NCOL]; // 32 MB e4m3
__device__ __align__(16) __half  g_e16[(size_t)NBATCH * NROW * NROW];// 32 MB fp16
__device__ uint32_t g_rowmin_u[NBATCH * NROW];

__device__ __forceinline__ uint32_t fkey(float f) {
    uint32_t u = __float_as_uint(f);
    return (u & 0x80000000u) ? ~u : (u | 0x80000000u);
}
__device__ __forceinline__ float fdecode(uint32_t k) {
    return (k & 0x80000000u) ? __uint_as_float(k ^ 0x80000000u) : __uint_as_float(~k);
}

// ---------------- kernel 1: space_to_channel pack + fp8 quantize -----------
__global__ void __launch_bounds__(256) pack_kernel(const float* __restrict__ x) {
    unsigned tid = blockIdx.x * 256u + threadIdx.x;
    if (tid < NBATCH * NROW) g_rowmin_u[tid] = 0xFFFFFFFFu;
    int d4 = tid & 15;
    int h  = (tid >> 4) & 63;
    int w  = (tid >> 10) & 63;
    int c  = (tid >> 16) & 31;
    int b  = tid >> 21;
    float4 v = reinterpret_cast<const float4*>(x)[tid];
    int n   = ((w >> 2) << 8) + (((w & 3) << 2) + (h >> 4)) * 16 + d4;
    int chb = ((h & 15) << 7) + c;
    size_t base = ((size_t)(b * NROW + chb)) * NCOL + n;
    float vv[4] = {v.x, v.y, v.z, v.w};
#pragma unroll
    for (int j = 0; j < 4; j++) {
        size_t idx = base + (size_t)j * 32 * NCOL;
        float f = vv[j];
        g_q[idx] = f;
        g_q8[idx] = (uint8_t)__nv_cvt_float_to_fp8(f, __NV_SATFINITE, __NV_E4M3);
    }
}

// ---------------- kernel 2: approx Gram (e4m3, fp32 accum) -----------------
// (byte-identical to R16: occ-2, fp16 epilogue tile, shuffle minima)
#define MMA_FP8(cacc, aa, bb) \
    asm volatile( \
        "mma.sync.aligned.m16n8k32.row.col.f32.e4m3.e4m3.f32 " \
        "{%0,%1,%2,%3},{%4,%5,%6,%7},{%8,%9},{%0,%1,%2,%3};\n" \
        : "+f"(cacc[0]), "+f"(cacc[1]), "+f"(cacc[2]), "+f"(cacc[3]) \
        : "r"(aa[0]), "r"(aa[1]), "r"(aa[2]), "r"(aa[3]), "r"(bb[0]), "r"(bb[1]))

__global__ void __launch_bounds__(256, 2) gram_kernel() {
    int b = blockIdx.y;
    int t = blockIdx.x;
    int ti = 0;
    while (t >= 16 - ti) { t -= 16 - ti; ti++; }
    int tj = ti + t;                                  // ti <= tj

    extern __shared__ unsigned char smem_raw[];
    uint8_t* sm = (uint8_t*)smem_raw;
    const int ARR = 128 * 80;
    const int STG = 2 * ARR;

    int tid  = threadIdx.x;
    int lane = tid & 31;
    int warp = tid >> 5;
    int wm = warp >> 2;
    int wn = warp & 3;

    size_t rowA = (size_t)(b * NROW + ti * 128);
    size_t rowB = (size_t)(b * NROW + tj * 128);

    auto load_stage = [&](int stage, int chunk) {
#pragma unroll
        for (int it = 0; it < 4; it++) {
            int u   = it * 256 + tid;
            int arr = u >> 9;
            int rr  = (u >> 2) & 127;
            int seg = (u & 3);
            size_t row = (arr ? rowB : rowA) + rr;
            const uint8_t* gp = g_q8 + row * NCOL + chunk * 64 + seg * 16;
            unsigned sp = (unsigned)__cvta_generic_to_shared(
                sm + stage * STG + arr * ARR + rr * 80 + seg * 16);
            asm volatile("cp.async.cg.shared.global [%0], [%1], 16;\n"
                         :: "r"(sp), "l"(gp));
        }
    };

    float acc[4][4][4];
#pragma unroll
    for (int a = 0; a < 4; a++)
#pragma unroll
        for (int bq = 0; bq < 4; bq++)
#pragma unroll
            for (int r = 0; r < 4; r++) acc[a][bq][r] = 0.f;

    const int KT = NCOL / 64;
    load_stage(0, 0);
    asm volatile("cp.async.commit_group;\n");
    load_stage(1, 1);
    asm volatile("cp.async.commit_group;\n");

    for (int kt = 0; kt < KT; kt++) {
        if (kt + 2 < KT) {
            load_stage((kt + 2) % 3, kt + 2);
            asm volatile("cp.async.commit_group;\n");
            asm volatile("cp.async.wait_group 2;\n");
        } else if (kt + 1 < KT) {
            asm volatile("cp.async.wait_group 1;\n");
        } else {
            asm volatile("cp.async.wait_group 0;\n");
        }
        __syncthreads();
        const uint8_t* st = sm + (kt % 3) * STG;

#pragma unroll
        for (int ks = 0; ks < 2; ks++) {
            unsigned ahi[4][4], bhi[4][2];
#pragma unroll
            for (int mt = 0; mt < 4; mt++) {
                int r    = wm * 64 + mt * 16 + (lane & 15);
                int coff = ks * 32 + ((lane >> 4) << 4);
                unsigned ah = (unsigned)__cvta_generic_to_shared(st + r * 80 + coff);
                asm volatile("ldmatrix.sync.aligned.m8n8.x4.shared.b16 {%0,%1,%2,%3}, [%4];\n"
                    : "=r"(ahi[mt][0]), "=r"(ahi[mt][1]), "=r"(ahi[mt][2]), "=r"(ahi[mt][3])
                    : "r"(ah));
            }
#pragma unroll
            for (int nt = 0; nt < 4; nt++) {
                int lb   = lane & 15;
                int r    = wn * 32 + nt * 8 + (lb & 7);
                int coff = ks * 32 + (((lb >> 3) & 1) << 4);
                unsigned bh = (unsigned)__cvta_generic_to_shared(st + ARR + r * 80 + coff);
                asm volatile("ldmatrix.sync.aligned.m8n8.x2.shared.b16 {%0,%1}, [%2];\n"
                    : "=r"(bhi[nt][0]), "=r"(bhi[nt][1]) : "r"(bh));
            }
#pragma unroll
            for (int mt = 0; mt < 4; mt++)
#pragma unroll
                for (int nt = 0; nt < 4; nt++)
                    MMA_FP8(acc[mt][nt], ahi[mt], bhi[nt]);
        }
        __syncthreads();
    }

    // ---- epilogue: fp16 tile in smem + register-shuffle minima ----
    uint32_t* hs     = (uint32_t*)smem_raw;   // 128 x 66 uint32 (fp16x2 tile)
    __half*   hh     = (__half*)hs;           // same, half view (stride 132)
    uint32_t* s_rmin = hs + 128 * 66;         // 128
    uint32_t* s_cmin = s_rmin + 128;          // 128

    if (tid < 128) s_rmin[tid] = 0xFFFFFFFFu;
    else           s_cmin[tid - 128] = 0xFFFFFFFFu;
    __syncthreads();

    int lr = lane >> 2, lc = (lane & 3) * 2;

#pragma unroll
    for (int mt = 0; mt < 4; mt++)
#pragma unroll
        for (int nt = 0; nt < 4; nt++) {
            int r = wm * 64 + mt * 16 + lr;
            int c = wn * 32 + nt * 8 + lc;
            __half2 h0 = __floats2half2_rn(acc[mt][nt][0], acc[mt][nt][1]);
            __half2 h1 = __floats2half2_rn(acc[mt][nt][2], acc[mt][nt][3]);
            *reinterpret_cast<__half2*>(&hs[r * 66 + (c >> 1)])       = h0;
            *reinterpret_cast<__half2*>(&hs[(r + 8) * 66 + (c >> 1)]) = h1;
        }

#pragma unroll
    for (int mt = 0; mt < 4; mt++) {
        float m0 = 3.4e38f, m1 = 3.4e38f;
#pragma unroll
        for (int nt = 0; nt < 4; nt++) {
            m0 = fminf(m0, fminf(acc[mt][nt][0], acc[mt][nt][1]));
            m1 = fminf(m1, fminf(acc[mt][nt][2], acc[mt][nt][3]));
        }
        m0 = fminf(m0, __shfl_xor_sync(0xFFFFFFFFu, m0, 1));
        m0 = fminf(m0, __shfl_xor_sync(0xFFFFFFFFu, m0, 2));
        m1 = fminf(m1, __shfl_xor_sync(0xFFFFFFFFu, m1, 1));
        m1 = fminf(m1, __shfl_xor_sync(0xFFFFFFFFu, m1, 2));
        if ((lane & 3) == 0) {
            int r0 = wm * 64 + mt * 16 + lr;
            atomicMin(&s_rmin[r0],     fkey(m0));
            atomicMin(&s_rmin[r0 + 8], fkey(m1));
        }
    }
#pragma unroll
    for (int nt = 0; nt < 4; nt++) {
        float c0 = 3.4e38f, c1 = 3.4e38f;
#pragma unroll
        for (int mt = 0; mt < 4; mt++) {
            c0 = fminf(c0, fminf(acc[mt][nt][0], acc[mt][nt][2]));
            c1 = fminf(c1, fminf(acc[mt][nt][1], acc[mt][nt][3]));
        }
#pragma unroll
        for (int o = 4; o <= 16; o <<= 1) {
            c0 = fminf(c0, __shfl_xor_sync(0xFFFFFFFFu, c0, o));
            c1 = fminf(c1, __shfl_xor_sync(0xFFFFFFFFu, c1, o));
        }
        if (lane < 4) {
            int cc = wn * 32 + nt * 8 + lane * 2;
            atomicMin(&s_cmin[cc],     fkey(c0));
            atomicMin(&s_cmin[cc + 1], fkey(c1));
        }
    }
    __syncthreads();

    if (tid < 128) atomicMin(&g_rowmin_u[b * NROW + ti * 128 + tid], s_rmin[tid]);
    else if (ti != tj)
        atomicMin(&g_rowmin_u[b * NROW + tj * 128 + (tid - 128)], s_cmin[tid - 128]);

    size_t ebase = (size_t)b * NROW * NROW;
    for (int u = tid; u < 8192; u += 256) {
        int r = u >> 6, c2 = u & 63;
        *reinterpret_cast<uint32_t*>(
            g_e16 + ebase + (size_t)(ti * 128 + r) * NROW + tj * 128 + 2 * c2) =
            hs[r * 66 + c2];
    }
    if (ti != tj) {
        for (int u = tid; u < 8192; u += 256) {
            int r = u >> 6, c2 = u & 63;
            __half2 hv = __halves2half2(hh[(2 * c2) * 132 + r], hh[(2 * c2 + 1) * 132 + r]);
            *reinterpret_cast<__half2*>(
                g_e16 + ebase + (size_t)(tj * 128 + r) * NROW + ti * 128 + 2 * c2) = hv;
        }
    }
}

// ---- kernel 3: FUSED scan + exact refine + softmax + sparse AV + c2s ------
// R16 fuse + (a) cnt==1 fast path (weight is identically 1 — skip dots),
// (b) combine-prune threshold 1e-5.
__global__ void __launch_bounds__(512) fuse_kernel(const float* __restrict__ gamma_ptr,
                                                   float* __restrict__ out) {
    int blk = blockIdx.x;               // 2048 blocks
    int cs = blk & 31;
    int e2 = (blk >> 5) & 15;
    int b  = blk >> 9;
    int t = threadIdx.x;
    int lane = t & 31;
    float gamma = __ldg(gamma_ptr);

    __shared__ int   cidx[4 * CMAX];
    __shared__ float exd [4 * CMAX];
    __shared__ int   cnts[4];

    int rl[4];
#pragma unroll
    for (int e1 = 0; e1 < 4; e1++) rl[e1] = e2 * 128 + e1 * 32 + cs;

    if (t < 4) cnts[t] = 0;
    if (t < 4 * CMAX) exd[t] = 0.f;
    __syncthreads();

    // candidate collect from fp16 energy rows (exact global threshold)
#pragma unroll
    for (int e1 = 0; e1 < 4; e1++) {
        int grow = b * NROW + rl[e1];
        float thr = fdecode(g_rowmin_u[grow]) + CUT;
        uint2 ev = reinterpret_cast<const uint2*>(g_e16 + (size_t)grow * NROW)[t];
        uint32_t ww[2] = {ev.x, ev.y};
#pragma unroll
        for (int p = 0; p < 2; p++) {
            __half2 h2 = *reinterpret_cast<__half2*>(&ww[p]);
            float e0 = __low2float(h2), e1v = __high2float(h2);
            if (e0 < thr) {
                int pos = atomicAdd(&cnts[e1], 1);
                if (pos < CMAX) cidx[e1 * CMAX + pos] = t * 4 + 2 * p;
            }
            if (e1v < thr) {
                int pos = atomicAdd(&cnts[e1], 1);
                if (pos < CMAX) cidx[e1 * CMAX + pos] = t * 4 + 2 * p + 1;
            }
        }
    }
    __syncthreads();

    const float4* qb4 = reinterpret_cast<const float4*>(g_q + (size_t)b * NROW * NCOL);

    // Phase A: exact fp32 dots, block-wide; cnt==1 needs no dot (weight == 1,
    // and Phase B yields exactly that from the zero-initialized logit).
#pragma unroll
    for (int e1 = 0; e1 < 4; e1++) {
        int cnt = cnts[e1]; if (cnt > CMAX) cnt = CMAX;
        if (cnt < 2) continue;
        const float4* qi = qb4 + (size_t)rl[e1] * 1024;
        float4 a0 = __ldg(qi + t);
        float4 a1 = __ldg(qi + t + 512);
        for (int k = 0; k < cnt; k++) {
            const float4* qj = qb4 + (size_t)cidx[e1 * CMAX + k] * 1024;
            float4 v0 = __ldg(qj + t);
            float4 v1 = __ldg(qj + t + 512);
            float s = a0.x * v0.x + a0.y * v0.y + a0.z * v0.z + a0.w * v0.w
                    + a1.x * v1.x + a1.y * v1.y + a1.z * v1.z + a1.w * v1.w;
#pragma unroll
            for (int o = 16; o > 0; o >>= 1) s += __shfl_xor_sync(0xFFFFFFFFu, s, o);
            if (lane == 0) atomicAdd(&exd[e1 * CMAX + k], s);
        }
    }
    __syncthreads();

    // Phase B: softmax + prune (one thread per e1, in-place compaction)
    if (t < 4) {
        int e1 = t;
        int cnt = cnts[e1]; if (cnt > CMAX) cnt = CMAX;
        float m = 3.4e38f;
        for (int c = 0; c < cnt; c++) m = fminf(m, exd[e1 * CMAX + c]);
        float Z = 0.f;
        for (int c = 0; c < cnt; c++) {
            float w = __expf(m - exd[e1 * CMAX + c]);
            exd[e1 * CMAX + c] = w; Z += w;
        }
        float inv = 1.0f / Z;
        int newc = 0;
        for (int c = 0; c < cnt; c++) {
            float w = exd[e1 * CMAX + c] * inv;
            if (w > 1e-5f) {
                cidx[e1 * CMAX + newc] = cidx[e1 * CMAX + c];
                exd [e1 * CMAX + newc] = w;
                newc++;
            }
        }
        cnts[e1] = newc;
    }
    __syncthreads();

    // Phase C: per-half weighted combine (rows L2-hot) + c2s store
    size_t obase = ((size_t)(b * 32 + cs)) * 64 * 64 * 64;
    int wq = e2 >> 2;
    int hq = (e2 & 3) * 16;

#pragma unroll
    for (int h = 0; h < 2; h++) {
        int f = h * 512 + t;               // float4 column 0..1023
        float res[4][4];
#pragma unroll
        for (int e1 = 0; e1 < 4; e1++) {
            int cnt = cnts[e1];
            float4 acc = make_float4(0.f, 0.f, 0.f, 0.f);
            for (int k = 0; k < cnt; k++) {
                float4 v = __ldg(&qb4[(size_t)cidx[e1 * CMAX + k] * 1024 + f]);
                float w = exd[e1 * CMAX + k];
                acc.x += w * v.x; acc.y += w * v.y;
                acc.z += w * v.z; acc.w += w * v.w;
            }
            float4 y = __ldg(&qb4[(size_t)rl[e1] * 1024 + f]);
            res[e1][0] = gamma * acc.x + y.x;
            res[e1][1] = gamma * acc.y + y.y;
            res[e1][2] = gamma * acc.z + y.z;
            res[e1][3] = gamma * acc.w + y.w;
        }
        int n0 = f * 4;
        int wd = n0 >> 8, hd = (n0 >> 4) & 15, dd0 = n0 & 15;
        int Wn = wd * 4 + wq;
        int Hn = hq + hd;
        size_t oi = obase + (size_t)Wn * 4096 + (size_t)Hn * 64 + dd0 * 4;
#pragma unroll
        for (int nn = 0; nn < 4; nn++) {
            *reinterpret_cast<float4*>(out + oi + nn * 4) =
                make_float4(res[0][nn], res[1][nn], res[2][nn], res[3][nn]);
        }
    }
}

// ---------------- launch ---------------------------------------------------
extern "C" void kernel_launch(void* const* d_in, const int* in_sizes, int n_in,
                              void* d_out, int out_size) {
    const float* x     = (const float*)d_in[0];
    const float* gamma = (const float*)d_in[1];
    float* out = (float*)d_out;

    pack_kernel<<<32768, 256>>>(x);

    cudaFuncSetAttribute(gram_kernel, cudaFuncAttributeMaxDynamicSharedMemorySize, 61440);
    gram_kernel<<<dim3(136, 4), 256, 61440>>>();

    fuse_kernel<<<2048, 512>>>(gamma, out);
}